// round 15
// baseline (speedup 1.0000x reference)
#include <cuda_runtime.h>
#include <cuda_fp16.h>
#include <cstdint>

// VACF via band-Gram, parallelogram tiling, mma.sync fp16 single-pass.
// R13 shell (K=64 chunks, cp.async f32 staging, per-thread convert, one
// barrier/chunk, 148 CTAs chunk-balanced) + batched ldsm: all 5 ldsm of a
// kstep issued before any mma, so only one smem latency is exposed per kstep.

#define T_DIM 10000
#define D_DIM 3000
#define D4    750
#define NTILE 79
#define NCHT  47                 // K chunks of 64 elems
#define UNITS (NTILE * NCHT)     // 3713
#define NCTA  148
#define NTHREADS 512
#define W_MAX 100
#define RB    240
#define F32_ROW 256              // 64 f32 = 256 B per staging row
#define F32_B   (RB * F32_ROW)   // 61440
#define STRB    144              // fp16 row stride: 128 B data + 16 pad
#define HTILE_B (RB * STRB)      // 34560
#define SMEM_B  (F32_B + 2 * HTILE_B)   // 130560
#define NSLOT   (RB * 16)        // 3840 16-byte staging slots

__device__ double g_band[128];
__device__ unsigned g_done;

__device__ __forceinline__ void ldsm4(unsigned a, unsigned& r0, unsigned& r1,
                                      unsigned& r2, unsigned& r3) {
    asm volatile("ldmatrix.sync.aligned.m8n8.x4.shared.b16 {%0,%1,%2,%3}, [%4];"
                 : "=r"(r0), "=r"(r1), "=r"(r2), "=r"(r3) : "r"(a));
}

__device__ __forceinline__ void mma16816h(float* c, const unsigned* a, const unsigned* b) {
    asm("mma.sync.aligned.m16n8k16.row.col.f32.f16.f16.f32 "
        "{%0,%1,%2,%3}, {%4,%5,%6,%7}, {%8,%9}, {%0,%1,%2,%3};"
        : "+f"(c[0]), "+f"(c[1]), "+f"(c[2]), "+f"(c[3])
        : "r"(a[0]), "r"(a[1]), "r"(a[2]), "r"(a[3]), "r"(b[0]), "r"(b[1]));
}

#define CPA16Z(dst, src, z) \
    asm volatile("cp.async.cg.shared.global [%0], [%1], 16, %2;" \
                 :: "r"(dst), "l"(src), "r"(z))

__global__ __launch_bounds__(NTHREADS, 1) void vacf_gram(const float* __restrict__ vel,
                                                         float* __restrict__ out, int W) {
    extern __shared__ __align__(128) char sm[];
    __shared__ float s_band[W_MAX];
    __shared__ int s_last;

    const int tid  = threadIdx.x;
    const int warp = tid >> 5;
    const int lane = tid & 31;
    const int gB   = blockIdx.x;

    const unsigned smu = (unsigned)__cvta_generic_to_shared(sm);
    const unsigned bf0 = smu + F32_B;

    if (tid < W_MAX) s_band[tid] = 0.f;

    const int strip = warp >> 1;             // 0..7
    const int njpb  = (warp & 1) * 4;        // 0 or 4
    const int rl = lane & 7, gg = lane >> 3;
    const int arow  = 16 * strip + rl + ((gg & 1) << 3);
    const int acol0 = (gg >> 1) << 3;
    const int brow0 = 16 * strip + rl + ((gg >> 1) << 3);
    const int bcol0 = (gg & 1) << 3;

    int u  = (int)(((long)gB * UNITS) / NCTA);
    const int u1 = (int)(((long)(gB + 1) * UNITS) / NCTA);

    float c[8][4];

    while (u < u1) {
        const int tile = u / NCHT;
        const int cbeg = u % NCHT;
        const int cend = (cbeg + (u1 - u) < NCHT) ? cbeg + (u1 - u) : NCHT;
        const int R0   = tile * 128;
        u += cend - cbeg;

        #pragma unroll
        for (int i = 0; i < 8; i++)
            #pragma unroll
            for (int q = 0; q < 4; q++) c[i][q] = 0.f;

        auto load_f32 = [&](int ci) {
            #pragma unroll
            for (int k = 0; k < 8; k++) {
                int sid = tid + (k << 9);
                if (sid < NSLOT) {
                    int row = sid >> 4;
                    int seg = sid & 15;
                    int gr  = R0 + row;
                    int c4  = ci * 16 + seg;
                    unsigned ok = (gr < T_DIM && c4 < D4) ? 16u : 0u;
                    const float* gp = vel + ((size_t)(gr < T_DIM ? gr : 0)) * D_DIM
                                          + (c4 < D4 ? c4 : 0) * 4;
                    CPA16Z(smu + (unsigned)(row * F32_ROW + seg * 16), gp, ok);
                }
            }
            asm volatile("cp.async.commit_group;" ::: "memory");
        };

        auto convert = [&](int stw) {
            const unsigned hib = F32_B + stw * HTILE_B;
            #pragma unroll 4
            for (int k = 0; k < 8; k++) {
                int sid = tid + (k << 9);
                if (sid < NSLOT) {
                    int row = sid >> 4;
                    int seg = sid & 15;
                    const float4 v = *reinterpret_cast<const float4*>(
                        sm + (row * F32_ROW + seg * 16));
                    __half2 h01 = __float22half2_rn(make_float2(v.x, v.y));
                    __half2 h23 = __float22half2_rn(make_float2(v.z, v.w));
                    uint2 hh;
                    hh.x = *reinterpret_cast<unsigned*>(&h01);
                    hh.y = *reinterpret_cast<unsigned*>(&h23);
                    *reinterpret_cast<uint2*>(sm + hib + (row * STRB + seg * 8)) = hh;
                }
            }
        };

        // batched kstep: 5 ldsm issued back-to-back, then 8 mma
        auto kstep = [&](unsigned hib, int kk) {
            unsigned a[4], b[4][4];
            unsigned aoff = (unsigned)(arow * STRB + (kk + acol0) * 2);
            ldsm4(hib + aoff, a[0], a[1], a[2], a[3]);
            #pragma unroll
            for (int jl = 0; jl < 4; jl++) {
                unsigned boff = (unsigned)((brow0 + (njpb + jl) * 16) * STRB
                                           + (kk + bcol0) * 2);
                ldsm4(hib + boff, b[jl][0], b[jl][1], b[jl][2], b[jl][3]);
            }
            #pragma unroll
            for (int jl = 0; jl < 4; jl++) {
                const int njp = njpb + jl;
                const int lj = jl * 2;
                mma16816h(c[lj], a, &b[jl][0]);
                if ((njp * 2 + 1) < 15) mma16816h(c[lj + 1], a, &b[jl][2]);
            }
        };

        // ---- prologue ----
        load_f32(cbeg);
        asm volatile("cp.async.wait_group 0;" ::: "memory");
        convert(0);
        if (cbeg + 1 < cend) load_f32(cbeg + 1);
        __syncthreads();

        for (int ci = cbeg; ci < cend; ci++) {
            const int st  = (ci - cbeg) & 1;
            const unsigned hib = bf0 + st * HTILE_B;

            kstep(hib, 0);
            kstep(hib, 16);

            // convert next chunk at fragment-quiet point (no barrier)
            if (ci + 1 < cend) {
                asm volatile("cp.async.wait_group 0;" ::: "memory");
                convert(st ^ 1);
                if (ci + 2 < cend) load_f32(ci + 2);
            }

            kstep(hib, 32);
            kstep(hib, 48);

            __syncthreads();
        }

        // ---- segment epilogue: band extraction ----
        #pragma unroll
        for (int jl = 0; jl < 4; jl++)
            #pragma unroll
            for (int j = 0; j < 2; j++) {
                const int nj = (njpb + jl) * 2 + j;
                if (nj < 15)
                    #pragma unroll
                    for (int q = 0; q < 4; q++) {
                        int t = nj * 8 + ((lane & 3) << 1) + (q & 1)
                              - (lane >> 2) - ((q >> 1) << 3);
                        if (t >= 0 && t < W_MAX)
                            atomicAdd(&s_band[t], c[jl * 2 + j][q]);
                    }
            }
        __syncthreads();
        if (tid < W_MAX) {
            atomicAdd(&g_band[tid], (double)s_band[tid]);
            s_band[tid] = 0.f;
        }
        __syncthreads();
    }

    // ---- completion protocol: last CTA finalizes ----
    if (tid == 0) {
        __threadfence();
        unsigned p = atomicAdd(&g_done, 1u);
        s_last = (p == NCTA - 1);
    }
    __syncthreads();
    if (s_last) {
        __threadfence();
        if (tid < W_MAX && tid < W)
            out[tid] = (float)(g_band[tid] / ((double)(T_DIM - tid) * (double)D_DIM));
        if (tid < 128) g_band[tid] = 0.0;
        if (tid == 0) g_done = 0;
    }
}

extern "C" void kernel_launch(void* const* d_in, const int* in_sizes, int n_in,
                              void* d_out, int out_size) {
    const float* vel = (const float*)d_in[0];
    cudaFuncSetAttribute(vacf_gram, cudaFuncAttributeMaxDynamicSharedMemorySize, SMEM_B);
    vacf_gram<<<NCTA, NTHREADS, SMEM_B>>>(vel, (float*)d_out, out_size);
}

// round 16
// speedup vs baseline: 1.5088x; 1.5088x over previous
#include <cuda_runtime.h>
#include <cuda_fp16.h>
#include <cstdint>

// VACF via band-Gram, parallelogram tiling, mma.sync fp16 single-pass.
// K-chunks of 128 elems (12.8 chunks/CTA -> half the barriers of R13), with
// the R13-proven cp.async 64-wide f32 staging used twice per chunk (two
// per-thread sub-waves: load s0 / convert half0 / load s1 / convert half1).
// 512 thr/CTA, 1 CTA/SM, 148 CTAs, chunk-balanced, last-CTA finalize.

#define T_DIM 10000
#define D_DIM 3000
#define D4    750
#define NTILE 79
#define NCHT  24                 // K chunks of 128 elems (24*128 = 3072)
#define UNITS (NTILE * NCHT)     // 1896
#define NCTA  148
#define NTHREADS 512
#define W_MAX 100
#define RB    240
#define F32_ROW 256              // 64-wide f32 staging: 256 B per row
#define F32_B   (RB * F32_ROW)   // 61440
#define STRB    272              // fp16 row stride: 256 B data + 16 pad
#define HTILE_B (RB * STRB)      // 65280
#define SMEM_B  (F32_B + 2 * HTILE_B)   // 192000
#define NSLOT   (RB * 16)        // 3840 16-byte staging slots (7.5/thread)

__device__ double g_band[128];
__device__ unsigned g_done;

__device__ __forceinline__ void ldsm4(unsigned a, unsigned& r0, unsigned& r1,
                                      unsigned& r2, unsigned& r3) {
    asm volatile("ldmatrix.sync.aligned.m8n8.x4.shared.b16 {%0,%1,%2,%3}, [%4];"
                 : "=r"(r0), "=r"(r1), "=r"(r2), "=r"(r3) : "r"(a));
}

__device__ __forceinline__ void mma16816h(float* c, const unsigned* a, const unsigned* b) {
    asm("mma.sync.aligned.m16n8k16.row.col.f32.f16.f16.f32 "
        "{%0,%1,%2,%3}, {%4,%5,%6,%7}, {%8,%9}, {%0,%1,%2,%3};"
        : "+f"(c[0]), "+f"(c[1]), "+f"(c[2]), "+f"(c[3])
        : "r"(a[0]), "r"(a[1]), "r"(a[2]), "r"(a[3]), "r"(b[0]), "r"(b[1]));
}

#define CPA16Z(dst, src, z) \
    asm volatile("cp.async.cg.shared.global [%0], [%1], 16, %2;" \
                 :: "r"(dst), "l"(src), "r"(z))

__global__ __launch_bounds__(NTHREADS, 1) void vacf_gram(const float* __restrict__ vel,
                                                         float* __restrict__ out, int W) {
    extern __shared__ __align__(128) char sm[];
    __shared__ float s_band[W_MAX];
    __shared__ int s_last;

    const int tid  = threadIdx.x;
    const int warp = tid >> 5;
    const int lane = tid & 31;
    const int gB   = blockIdx.x;

    const unsigned smu = (unsigned)__cvta_generic_to_shared(sm);
    const unsigned bf0 = smu + F32_B;

    if (tid < W_MAX) s_band[tid] = 0.f;

    const int strip = warp >> 1;             // 0..7
    const int njpb  = (warp & 1) * 4;        // 0 or 4
    const int rl = lane & 7, gg = lane >> 3;
    const int arow  = 16 * strip + rl + ((gg & 1) << 3);
    const int acol0 = (gg >> 1) << 3;
    const int brow0 = 16 * strip + rl + ((gg >> 1) << 3);
    const int bcol0 = (gg & 1) << 3;

    int u  = (int)(((long)gB * UNITS) / NCTA);
    const int u1 = (int)(((long)(gB + 1) * UNITS) / NCTA);

    float c[8][4];

    while (u < u1) {
        const int tile = u / NCHT;
        const int cbeg = u % NCHT;
        const int cend = (cbeg + (u1 - u) < NCHT) ? cbeg + (u1 - u) : NCHT;
        const int R0   = tile * 128;
        u += cend - cbeg;

        #pragma unroll
        for (int i = 0; i < 8; i++)
            #pragma unroll
            for (int q = 0; q < 4; q++) c[i][q] = 0.f;

        // staging slot: sid = tid + 512k (k<8, sid<3840): row = sid>>4, seg = sid&15
        // sub-wave h of chunk ci covers f32 groups c4 = ci*32 + h*16 + seg
        auto load_sub = [&](int ci, int h) {
            #pragma unroll
            for (int k = 0; k < 8; k++) {
                int sid = tid + (k << 9);
                if (sid < NSLOT) {
                    int row = sid >> 4;
                    int seg = sid & 15;
                    int gr  = R0 + row;
                    int c4  = ci * 32 + h * 16 + seg;
                    unsigned ok = (gr < T_DIM && c4 < D4) ? 16u : 0u;
                    const float* gp = vel + ((size_t)(gr < T_DIM ? gr : 0)) * D_DIM
                                          + (c4 < D4 ? c4 : 0) * 4;
                    CPA16Z(smu + (unsigned)(row * F32_ROW + seg * 16), gp, ok);
                }
            }
            asm volatile("cp.async.commit_group;" ::: "memory");
        };

        // staging -> fp16 stage stw, half h; per-thread slots, no barrier
        auto convert = [&](int stw, int h) {
            const unsigned hib = F32_B + stw * HTILE_B + h * 128;
            #pragma unroll 4
            for (int k = 0; k < 8; k++) {
                int sid = tid + (k << 9);
                if (sid < NSLOT) {
                    int row = sid >> 4;
                    int seg = sid & 15;
                    const float4 v = *reinterpret_cast<const float4*>(
                        sm + (row * F32_ROW + seg * 16));
                    __half2 h01 = __float22half2_rn(make_float2(v.x, v.y));
                    __half2 h23 = __float22half2_rn(make_float2(v.z, v.w));
                    uint2 hh;
                    hh.x = *reinterpret_cast<unsigned*>(&h01);
                    hh.y = *reinterpret_cast<unsigned*>(&h23);
                    *reinterpret_cast<uint2*>(sm + hib + (row * STRB + seg * 8)) = hh;
                }
            }
        };

        // R13-form kstep: serial ldsm -> mma per jl (proven fastest)
        auto kstep = [&](unsigned hib, int kk) {
            unsigned aoff = (unsigned)(arow * STRB + (kk + acol0) * 2);
            unsigned a[4];
            ldsm4(hib + aoff, a[0], a[1], a[2], a[3]);
            #pragma unroll
            for (int jl = 0; jl < 4; jl++) {
                const int njp = njpb + jl;
                unsigned boff = (unsigned)((brow0 + njp * 16) * STRB + (kk + bcol0) * 2);
                unsigned b[4];
                ldsm4(hib + boff, b[0], b[1], b[2], b[3]);
                const int lj = jl * 2;
                mma16816h(c[lj], a, &b[0]);
                if ((njp * 2 + 1) < 15) mma16816h(c[lj + 1], a, &b[2]);
            }
        };

        // ---- prologue: stage chunk cbeg into stage 0 (both halves) ----
        load_sub(cbeg, 0);
        asm volatile("cp.async.wait_group 0;" ::: "memory");
        convert(0, 0);
        load_sub(cbeg, 1);
        asm volatile("cp.async.wait_group 0;" ::: "memory");
        convert(0, 1);
        if (cbeg + 1 < cend) load_sub(cbeg + 1, 0);
        __syncthreads();

        for (int ci = cbeg; ci < cend; ci++) {
            const int st  = (ci - cbeg) & 1;
            const unsigned hib = bf0 + st * HTILE_B;
            const bool havenext = (ci + 1 < cend);

            kstep(hib, 0);
            kstep(hib, 16);

            if (havenext) {
                asm volatile("cp.async.wait_group 0;" ::: "memory");
                convert(st ^ 1, 0);
                load_sub(ci + 1, 1);
            }

            kstep(hib, 32);
            kstep(hib, 48);
            kstep(hib, 64);

            if (havenext) {
                asm volatile("cp.async.wait_group 0;" ::: "memory");
                convert(st ^ 1, 1);
                if (ci + 2 < cend) load_sub(ci + 2, 0);
            }

            kstep(hib, 80);
            kstep(hib, 96);
            kstep(hib, 112);

            // single barrier per chunk: publishes stage st^1, retires stage st
            __syncthreads();
        }

        // ---- segment epilogue: band extraction ----
        #pragma unroll
        for (int jl = 0; jl < 4; jl++)
            #pragma unroll
            for (int j = 0; j < 2; j++) {
                const int nj = (njpb + jl) * 2 + j;
                if (nj < 15)
                    #pragma unroll
                    for (int q = 0; q < 4; q++) {
                        int t = nj * 8 + ((lane & 3) << 1) + (q & 1)
                              - (lane >> 2) - ((q >> 1) << 3);
                        if (t >= 0 && t < W_MAX)
                            atomicAdd(&s_band[t], c[jl * 2 + j][q]);
                    }
            }
        __syncthreads();
        if (tid < W_MAX) {
            atomicAdd(&g_band[tid], (double)s_band[tid]);
            s_band[tid] = 0.f;
        }
        __syncthreads();
    }

    // ---- completion protocol: last CTA finalizes ----
    if (tid == 0) {
        __threadfence();
        unsigned p = atomicAdd(&g_done, 1u);
        s_last = (p == NCTA - 1);
    }
    __syncthreads();
    if (s_last) {
        __threadfence();
        if (tid < W_MAX && tid < W)
            out[tid] = (float)(g_band[tid] / ((double)(T_DIM - tid) * (double)D_DIM));
        if (tid < 128) g_band[tid] = 0.0;
        if (tid == 0) g_done = 0;
    }
}

extern "C" void kernel_launch(void* const* d_in, const int* in_sizes, int n_in,
                              void* d_out, int out_size) {
    const float* vel = (const float*)d_in[0];
    cudaFuncSetAttribute(vacf_gram, cudaFuncAttributeMaxDynamicSharedMemorySize, SMEM_B);
    vacf_gram<<<NCTA, NTHREADS, SMEM_B>>>(vel, (float*)d_out, out_size);
}

// round 17
// speedup vs baseline: 1.6550x; 1.0969x over previous
#include <cuda_runtime.h>
#include <cuda_fp16.h>
#include <cstdint>

// VACF via band-Gram, parallelogram tiling, mma.sync fp16 single-pass.
// 1024 threads / 32 warps per CTA (8 warps/SMSP): each 16-row strip's band is
// split across 4 warps (2 njp each, 16 acc regs) to double latency hiding.
// K=128 chunks, cp.async 64-wide f32 staging twice per chunk, 1 barrier/chunk.
// 148 CTAs, chunk-balanced persistent grid, last-CTA finalize.

#define T_DIM 10000
#define D_DIM 3000
#define D4    750
#define NTILE 79
#define NCHT  24                 // K chunks of 128 elems
#define UNITS (NTILE * NCHT)     // 1896
#define NCTA  148
#define NTHREADS 1024
#define W_MAX 100
#define RB    240
#define F32_ROW 256              // 64-wide f32 staging: 256 B per row
#define F32_B   (RB * F32_ROW)   // 61440
#define STRB    272              // fp16 row stride: 256 B data + 16 pad
#define HTILE_B (RB * STRB)      // 65280
#define SMEM_B  (F32_B + 2 * HTILE_B)   // 192000
#define NSLOT   (RB * 16)        // 3840 16-byte staging slots

__device__ double g_band[128];
__device__ unsigned g_done;

__device__ __forceinline__ void ldsm4(unsigned a, unsigned& r0, unsigned& r1,
                                      unsigned& r2, unsigned& r3) {
    asm volatile("ldmatrix.sync.aligned.m8n8.x4.shared.b16 {%0,%1,%2,%3}, [%4];"
                 : "=r"(r0), "=r"(r1), "=r"(r2), "=r"(r3) : "r"(a));
}

__device__ __forceinline__ void mma16816h(float* c, const unsigned* a, const unsigned* b) {
    asm("mma.sync.aligned.m16n8k16.row.col.f32.f16.f16.f32 "
        "{%0,%1,%2,%3}, {%4,%5,%6,%7}, {%8,%9}, {%0,%1,%2,%3};"
        : "+f"(c[0]), "+f"(c[1]), "+f"(c[2]), "+f"(c[3])
        : "r"(a[0]), "r"(a[1]), "r"(a[2]), "r"(a[3]), "r"(b[0]), "r"(b[1]));
}

#define CPA16Z(dst, src, z) \
    asm volatile("cp.async.cg.shared.global [%0], [%1], 16, %2;" \
                 :: "r"(dst), "l"(src), "r"(z))

__global__ __launch_bounds__(NTHREADS, 1) void vacf_gram(const float* __restrict__ vel,
                                                         float* __restrict__ out, int W) {
    extern __shared__ __align__(128) char sm[];
    __shared__ float s_band[W_MAX];
    __shared__ int s_last;

    const int tid  = threadIdx.x;
    const int warp = tid >> 5;
    const int lane = tid & 31;
    const int gB   = blockIdx.x;

    const unsigned smu = (unsigned)__cvta_generic_to_shared(sm);
    const unsigned bf0 = smu + F32_B;

    if (tid < W_MAX) s_band[tid] = 0.f;

    const int strip = warp >> 2;             // 0..7: 16-row strip
    const int njpb  = (warp & 3) * 2;        // njp base: 0,2,4,6
    const int rl = lane & 7, gg = lane >> 3;
    const int arow  = 16 * strip + rl + ((gg & 1) << 3);
    const int acol0 = (gg >> 1) << 3;
    const int brow0 = 16 * strip + rl + ((gg >> 1) << 3);
    const int bcol0 = (gg & 1) << 3;

    int u  = (int)(((long)gB * UNITS) / NCTA);
    const int u1 = (int)(((long)(gB + 1) * UNITS) / NCTA);

    float c[4][4];                           // 2 njp x 2 nj x 4

    while (u < u1) {
        const int tile = u / NCHT;
        const int cbeg = u % NCHT;
        const int cend = (cbeg + (u1 - u) < NCHT) ? cbeg + (u1 - u) : NCHT;
        const int R0   = tile * 128;
        u += cend - cbeg;

        #pragma unroll
        for (int i = 0; i < 4; i++)
            #pragma unroll
            for (int q = 0; q < 4; q++) c[i][q] = 0.f;

        // staging slot: sid = tid + 1024k (k<4, sid<3840): row=sid>>4, seg=sid&15
        auto load_sub = [&](int ci, int h) {
            #pragma unroll
            for (int k = 0; k < 4; k++) {
                int sid = tid + (k << 10);
                if (sid < NSLOT) {
                    int row = sid >> 4;
                    int seg = sid & 15;
                    int gr  = R0 + row;
                    int c4  = ci * 32 + h * 16 + seg;
                    unsigned ok = (gr < T_DIM && c4 < D4) ? 16u : 0u;
                    const float* gp = vel + ((size_t)(gr < T_DIM ? gr : 0)) * D_DIM
                                          + (c4 < D4 ? c4 : 0) * 4;
                    CPA16Z(smu + (unsigned)(row * F32_ROW + seg * 16), gp, ok);
                }
            }
            asm volatile("cp.async.commit_group;" ::: "memory");
        };

        auto convert = [&](int stw, int h) {
            const unsigned hib = F32_B + stw * HTILE_B + h * 128;
            #pragma unroll
            for (int k = 0; k < 4; k++) {
                int sid = tid + (k << 10);
                if (sid < NSLOT) {
                    int row = sid >> 4;
                    int seg = sid & 15;
                    const float4 v = *reinterpret_cast<const float4*>(
                        sm + (row * F32_ROW + seg * 16));
                    __half2 h01 = __float22half2_rn(make_float2(v.x, v.y));
                    __half2 h23 = __float22half2_rn(make_float2(v.z, v.w));
                    uint2 hh;
                    hh.x = *reinterpret_cast<unsigned*>(&h01);
                    hh.y = *reinterpret_cast<unsigned*>(&h23);
                    *reinterpret_cast<uint2*>(sm + hib + (row * STRB + seg * 8)) = hh;
                }
            }
        };

        // R13-form kstep (serial ldsm -> mma), 2 njp per warp
        auto kstep = [&](unsigned hib, int kk) {
            unsigned aoff = (unsigned)(arow * STRB + (kk + acol0) * 2);
            unsigned a[4];
            ldsm4(hib + aoff, a[0], a[1], a[2], a[3]);
            #pragma unroll
            for (int jl = 0; jl < 2; jl++) {
                const int njp = njpb + jl;
                unsigned boff = (unsigned)((brow0 + njp * 16) * STRB + (kk + bcol0) * 2);
                unsigned b[4];
                ldsm4(hib + boff, b[0], b[1], b[2], b[3]);
                const int lj = jl * 2;
                mma16816h(c[lj], a, &b[0]);
                if ((njp * 2 + 1) < 15) mma16816h(c[lj + 1], a, &b[2]);
            }
        };

        // ---- prologue: stage chunk cbeg into stage 0 ----
        load_sub(cbeg, 0);
        asm volatile("cp.async.wait_group 0;" ::: "memory");
        convert(0, 0);
        load_sub(cbeg, 1);
        asm volatile("cp.async.wait_group 0;" ::: "memory");
        convert(0, 1);
        if (cbeg + 1 < cend) load_sub(cbeg + 1, 0);
        __syncthreads();

        for (int ci = cbeg; ci < cend; ci++) {
            const int st  = (ci - cbeg) & 1;
            const unsigned hib = bf0 + st * HTILE_B;
            const bool havenext = (ci + 1 < cend);

            kstep(hib, 0);
            kstep(hib, 16);

            if (havenext) {
                asm volatile("cp.async.wait_group 0;" ::: "memory");
                convert(st ^ 1, 0);
                load_sub(ci + 1, 1);
            }

            kstep(hib, 32);
            kstep(hib, 48);
            kstep(hib, 64);

            if (havenext) {
                asm volatile("cp.async.wait_group 0;" ::: "memory");
                convert(st ^ 1, 1);
                if (ci + 2 < cend) load_sub(ci + 2, 0);
            }

            kstep(hib, 80);
            kstep(hib, 96);
            kstep(hib, 112);

            // single barrier per chunk
            __syncthreads();
        }

        // ---- segment epilogue: band extraction ----
        #pragma unroll
        for (int jl = 0; jl < 2; jl++)
            #pragma unroll
            for (int j = 0; j < 2; j++) {
                const int nj = (njpb + jl) * 2 + j;
                if (nj < 15)
                    #pragma unroll
                    for (int q = 0; q < 4; q++) {
                        int t = nj * 8 + ((lane & 3) << 1) + (q & 1)
                              - (lane >> 2) - ((q >> 1) << 3);
                        if (t >= 0 && t < W_MAX)
                            atomicAdd(&s_band[t], c[jl * 2 + j][q]);
                    }
            }
        __syncthreads();
        if (tid < W_MAX) {
            atomicAdd(&g_band[tid], (double)s_band[tid]);
            s_band[tid] = 0.f;
        }
        __syncthreads();
    }

    // ---- completion protocol: last CTA finalizes ----
    if (tid == 0) {
        __threadfence();
        unsigned p = atomicAdd(&g_done, 1u);
        s_last = (p == NCTA - 1);
    }
    __syncthreads();
    if (s_last) {
        __threadfence();
        if (tid < W_MAX && tid < W)
            out[tid] = (float)(g_band[tid] / ((double)(T_DIM - tid) * (double)D_DIM));
        if (tid < 128) g_band[tid] = 0.0;
        if (tid == 0) g_done = 0;
    }
}

extern "C" void kernel_launch(void* const* d_in, const int* in_sizes, int n_in,
                              void* d_out, int out_size) {
    const float* vel = (const float*)d_in[0];
    cudaFuncSetAttribute(vacf_gram, cudaFuncAttributeMaxDynamicSharedMemorySize, SMEM_B);
    vacf_gram<<<NCTA, NTHREADS, SMEM_B>>>(vel, (float*)d_out, out_size);
}